// round 7
// baseline (speedup 1.0000x reference)
#include <cuda_runtime.h>
#include <cuda_bf16.h>
#include <cstdint>

// Circulant GEMM on mma.sync bf16: D[56,224] = A_c[56,56] @ X[56,224]
// per (channel, 4 batches). 3-term split Ah*Bh + Am*Bh + Ah*Bm.
// K = 3 x k16 tiles + 1 x k8 tail (no padding). B in natural [k][n] smem,
// ldmatrix.trans fetch; A circulant fragments in registers.

#define CCH 384
#define HW 56
#define PLANE 3136
#define NTHREADS 256
#define ROWB 496                      // 124 words/row, 124%32==28 -> conflict-free
#define CH_STRIDE (56 * ROWB)         // 27776 B per precision chunk
#define W_OFF (2 * CH_STRIDE)         // 55552
#define SMEM_TOTAL (W_OFF + 256)      // 55808  -> 4 blocks/SM

__device__ __forceinline__ uint32_t smem_u32(const void* p) {
    uint32_t a;
    asm("{ .reg .u64 t; cvta.to.shared.u64 t, %1; cvt.u32.u64 %0, t; }" : "=r"(a) : "l"(p));
    return a;
}
__device__ __forceinline__ void ldmat4t(uint32_t r[4], uint32_t addr) {
    asm volatile("ldmatrix.sync.aligned.m8n8.x4.trans.shared.b16 {%0,%1,%2,%3}, [%4];"
                 : "=r"(r[0]), "=r"(r[1]), "=r"(r[2]), "=r"(r[3]) : "r"(addr));
}
__device__ __forceinline__ void ldmat2t(uint32_t r[2], uint32_t addr) {
    asm volatile("ldmatrix.sync.aligned.m8n8.x2.trans.shared.b16 {%0,%1}, [%2];"
                 : "=r"(r[0]), "=r"(r[1]) : "r"(addr));
}
__device__ __forceinline__ void mma16(float c[4], const uint32_t a[4],
                                      uint32_t b0, uint32_t b1) {
    asm volatile(
        "mma.sync.aligned.m16n8k16.row.col.f32.bf16.bf16.f32 "
        "{%0,%1,%2,%3}, {%4,%5,%6,%7}, {%8,%9}, {%0,%1,%2,%3};"
        : "+f"(c[0]), "+f"(c[1]), "+f"(c[2]), "+f"(c[3])
        : "r"(a[0]), "r"(a[1]), "r"(a[2]), "r"(a[3]), "r"(b0), "r"(b1));
}
__device__ __forceinline__ void mma8(float c[4], const uint32_t a[2], uint32_t b0) {
    asm volatile(
        "mma.sync.aligned.m16n8k8.row.col.f32.bf16.bf16.f32 "
        "{%0,%1,%2,%3}, {%4,%5}, {%6}, {%0,%1,%2,%3};"
        : "+f"(c[0]), "+f"(c[1]), "+f"(c[2]), "+f"(c[3])
        : "r"(a[0]), "r"(a[1]), "r"(b0));
}
__device__ __forceinline__ uint32_t bits2(__nv_bfloat162 v) { return *(uint32_t*)&v; }

extern __shared__ char smem[];

__global__ __launch_bounds__(NTHREADS, 4)
void gcc_conv_hmma3(const float* __restrict__ x, const float* __restrict__ weight,
                    const float* __restrict__ bias, float* __restrict__ out) {
    const int tid = threadIdx.x;
    const int c  = blockIdx.x >> 3;
    const int b0 = (blockIdx.x & 7) * 4;

    float* wtab = (float*)(smem + W_OFF);
    if (tid < HW) wtab[tid] = weight[c * HW + tid];
    __syncthreads();

    const int wid = tid >> 5, lane = tid & 31;
    const int wm = wid & 3, wn = wid >> 2;
    const int g = lane >> 2, i4 = lane & 3;
    const int r0 = wm * 16 + g;          // < 56
    const int r1 = r0 + 8;               // >= 56 only when wm==3

    // ---- A circulant fragments (hi/mid): 3 k16 tiles + k8 tail ----
    uint32_t Ah[3][4], Am[3][4], Th[2], Tm[2];
#pragma unroll
    for (int kt = 0; kt < 3; kt++) {
#pragma unroll
        for (int reg = 0; reg < 4; reg++) {
            const int row = (reg & 1) ? r1 : r0;
            const int kk = kt * 16 + 2 * i4 + ((reg & 2) ? 8 : 0);
            float v0 = 0.f, v1 = 0.f;
            if (row < HW) {
                int j0 = kk - row; if (j0 < 0) j0 += HW;
                int j1 = j0 + 1;   if (j1 == HW) j1 = 0;
                v0 = wtab[j0]; v1 = wtab[j1];
            }
            __nv_bfloat162 h = __floats2bfloat162_rn(v0, v1);
            __nv_bfloat162 m = __floats2bfloat162_rn(v0 - __bfloat162float(h.x),
                                                     v1 - __bfloat162float(h.y));
            Ah[kt][reg] = bits2(h);
            Am[kt][reg] = bits2(m);
        }
    }
#pragma unroll
    for (int reg = 0; reg < 2; reg++) {
        const int row = reg ? r1 : r0;
        const int kk = 48 + 2 * i4;
        float v0 = 0.f, v1 = 0.f;
        if (row < HW) {
            int j0 = kk - row; if (j0 < 0) j0 += HW;
            int j1 = j0 + 1;   if (j1 == HW) j1 = 0;
            v0 = wtab[j0]; v1 = wtab[j1];
        }
        __nv_bfloat162 h = __floats2bfloat162_rn(v0, v1);
        __nv_bfloat162 m = __floats2bfloat162_rn(v0 - __bfloat162float(h.x),
                                                 v1 - __bfloat162float(h.y));
        Th[reg] = bits2(h);
        Tm[reg] = bits2(m);
    }

    // ---- convert pass: X -> natural [k][n] bf16 smem, hi & mid ----
    // unit (k, wq) identical across batches; hoist index math out of b loop.
    int kU[4], wqU[4];
#pragma unroll
    for (int i = 0; i < 4; i++) {
        const int u2 = tid + 256 * i;
        kU[i] = u2 / 14;
        wqU[i] = u2 - kU[i] * 14;
    }
    const float* xc = x + ((size_t)b0 * CCH + c) * PLANE;
#pragma unroll
    for (int b = 0; b < 4; b++) {
        const float* xb = xc + (size_t)b * CCH * PLANE;
        char* sb = smem + b * 112;
#pragma unroll
        for (int i = 0; i < 4; i++) {
            if (tid + 256 * i >= 784) break;
            const float4 v = *(const float4*)(xb + kU[i] * HW + wqU[i] * 4);
            __nv_bfloat162 h01 = __floats2bfloat162_rn(v.x, v.y);
            __nv_bfloat162 h23 = __floats2bfloat162_rn(v.z, v.w);
            __nv_bfloat162 m01 = __floats2bfloat162_rn(v.x - __bfloat162float(h01.x),
                                                       v.y - __bfloat162float(h01.y));
            __nv_bfloat162 m23 = __floats2bfloat162_rn(v.z - __bfloat162float(h23.x),
                                                       v.w - __bfloat162float(h23.y));
            char* p = sb + kU[i] * ROWB + wqU[i] * 8;
            *(uint2*)p = make_uint2(bits2(h01), bits2(h23));
            *(uint2*)(p + CH_STRIDE) = make_uint2(bits2(m01), bits2(m23));
        }
    }
    __syncthreads();

    // ---- MMA: warp = (m-quarter wm, n-half wn), 7 n-tile pairs ----
    const float bv = bias[c];
    const uint32_t sbase = smem_u32(smem);
    const int krow = (lane & 7) + ((lane >> 3) & 1) * 8;
    const int nsel = lane >> 4;
    const uint32_t lbase = sbase + krow * ROWB;                 // k16 tiles
    const uint32_t tbase = sbase + (48 + (lane & 7)) * ROWB;    // k8 tail
    const int tnsel = (lane >> 3) & 1;

#pragma unroll
    for (int np = 0; np < 7; np++) {
        const int nt0 = wn * 14 + np * 2;
        float acc0[4] = {bv, bv, bv, bv};
        float acc1[4] = {bv, bv, bv, bv};
        const uint32_t laddr = lbase + (uint32_t)(nt0 + nsel) * 16;
        const uint32_t taddr = tbase + (uint32_t)(nt0 + tnsel) * 16;
#pragma unroll
        for (int kt = 0; kt < 3; kt++) {
            uint32_t bh[4], bm[4];
            ldmat4t(bh, laddr + kt * 16 * ROWB);
            ldmat4t(bm, laddr + kt * 16 * ROWB + CH_STRIDE);
            mma16(acc0, Ah[kt], bh[0], bh[1]);
            mma16(acc1, Ah[kt], bh[2], bh[3]);
            mma16(acc0, Am[kt], bh[0], bh[1]);
            mma16(acc1, Am[kt], bh[2], bh[3]);
            mma16(acc0, Ah[kt], bm[0], bm[1]);
            mma16(acc1, Ah[kt], bm[2], bm[3]);
        }
        {   // k8 tail (rows 48..55)
            uint32_t bh[2], bm[2];
            ldmat2t(bh, taddr);
            ldmat2t(bm, taddr + CH_STRIDE);
            mma8(acc0, Th, bh[0]);
            mma8(acc1, Th, bh[1]);
            mma8(acc0, Tm, bh[0]);
            mma8(acc1, Tm, bh[1]);
            mma8(acc0, Th, bm[0]);
            mma8(acc1, Th, bm[1]);
        }
#pragma unroll
        for (int s = 0; s < 2; s++) {
            const float* acc = s ? acc1 : acc0;
            const int n = (nt0 + s) * 8 + 2 * i4;
            const int b = n / HW, wcol = n - b * HW;
            float* op = out + ((size_t)(b0 + b) * CCH + c) * PLANE + wcol;
            *(float2*)(op + r0 * HW) = make_float2(acc[0], acc[1]);
            if (wm != 3)
                *(float2*)(op + r1 * HW) = make_float2(acc[2], acc[3]);
        }
    }
}

extern "C" void kernel_launch(void* const* d_in, const int* in_sizes, int n_in,
                              void* d_out, int out_size) {
    const float* x      = (const float*)d_in[0];
    const float* weight = (const float*)d_in[1];
    const float* bias   = (const float*)d_in[2];
    cudaFuncSetAttribute(gcc_conv_hmma3,
                         cudaFuncAttributeMaxDynamicSharedMemorySize, SMEM_TOTAL);
    gcc_conv_hmma3<<<CCH * 8, NTHREADS, SMEM_TOTAL>>>(x, weight, bias, (float*)d_out);
}

// round 8
// speedup vs baseline: 1.1317x; 1.1317x over previous
#include <cuda_runtime.h>
#include <cuda_bf16.h>
#include <cstdint>

// Circulant GEMM on mma.sync bf16: D[56,224] = A_c[56,56] @ X[56,224]
// per (channel, 4 batches). 3-term split Ah*Bh + Am*Bh + Ah*Bm.
// K = 3 x k16 + k8 tail. B in natural [k][n] smem, ldmatrix.trans fetch,
// register double-buffered across kt. A circulant fragments in registers.

#define CCH 384
#define HW 56
#define PLANE 3136
#define NTHREADS 256
#define ROWB 496                      // 124 words/row, 124%32==28 -> conflict-free
#define CH_STRIDE (56 * ROWB)         // 27776 B per precision chunk
#define W_OFF (2 * CH_STRIDE)         // 55552
#define SMEM_TOTAL (W_OFF + 256)      // 55808

__device__ __forceinline__ uint32_t smem_u32(const void* p) {
    uint32_t a;
    asm("{ .reg .u64 t; cvta.to.shared.u64 t, %1; cvt.u32.u64 %0, t; }" : "=r"(a) : "l"(p));
    return a;
}
__device__ __forceinline__ void ldmat4t(uint32_t r[4], uint32_t addr) {
    asm volatile("ldmatrix.sync.aligned.m8n8.x4.trans.shared.b16 {%0,%1,%2,%3}, [%4];"
                 : "=r"(r[0]), "=r"(r[1]), "=r"(r[2]), "=r"(r[3]) : "r"(addr));
}
__device__ __forceinline__ void ldmat2t(uint32_t r[2], uint32_t addr) {
    asm volatile("ldmatrix.sync.aligned.m8n8.x2.trans.shared.b16 {%0,%1}, [%2];"
                 : "=r"(r[0]), "=r"(r[1]) : "r"(addr));
}
__device__ __forceinline__ void mma16(float c[4], const uint32_t a[4],
                                      uint32_t b0, uint32_t b1) {
    asm volatile(
        "mma.sync.aligned.m16n8k16.row.col.f32.bf16.bf16.f32 "
        "{%0,%1,%2,%3}, {%4,%5,%6,%7}, {%8,%9}, {%0,%1,%2,%3};"
        : "+f"(c[0]), "+f"(c[1]), "+f"(c[2]), "+f"(c[3])
        : "r"(a[0]), "r"(a[1]), "r"(a[2]), "r"(a[3]), "r"(b0), "r"(b1));
}
__device__ __forceinline__ void mma8(float c[4], const uint32_t a[2], uint32_t b0) {
    asm volatile(
        "mma.sync.aligned.m16n8k8.row.col.f32.bf16.bf16.f32 "
        "{%0,%1,%2,%3}, {%4,%5}, {%6}, {%0,%1,%2,%3};"
        : "+f"(c[0]), "+f"(c[1]), "+f"(c[2]), "+f"(c[3])
        : "r"(a[0]), "r"(a[1]), "r"(b0));
}
__device__ __forceinline__ uint32_t bits2(__nv_bfloat162 v) { return *(uint32_t*)&v; }

extern __shared__ char smem[];

__global__ __launch_bounds__(NTHREADS, 3)
void gcc_conv_hmma4(const float* __restrict__ x, const float* __restrict__ weight,
                    const float* __restrict__ bias, float* __restrict__ out) {
    const int tid = threadIdx.x;
    const int c  = blockIdx.x >> 3;
    const int b0 = (blockIdx.x & 7) * 4;

    float* wtab = (float*)(smem + W_OFF);
    if (tid < HW) wtab[tid] = weight[c * HW + tid];
    __syncthreads();

    const int wid = tid >> 5, lane = tid & 31;
    const int wm = wid & 3, wn = wid >> 2;
    const int g = lane >> 2, i4 = lane & 3;
    const int r0 = wm * 16 + g;          // < 56
    const int r1 = r0 + 8;               // >= 56 only when wm==3

    // ---- A circulant fragments (hi/mid): 3 k16 tiles + k8 tail ----
    uint32_t Ah[3][4], Am[3][4], Th[2], Tm[2];
#pragma unroll
    for (int kt = 0; kt < 3; kt++) {
#pragma unroll
        for (int reg = 0; reg < 4; reg++) {
            const int row = (reg & 1) ? r1 : r0;
            const int kk = kt * 16 + 2 * i4 + ((reg & 2) ? 8 : 0);
            float v0 = 0.f, v1 = 0.f;
            if (row < HW) {
                int j0 = kk - row; if (j0 < 0) j0 += HW;
                int j1 = j0 + 1;   if (j1 == HW) j1 = 0;
                v0 = wtab[j0]; v1 = wtab[j1];
            }
            __nv_bfloat162 h = __floats2bfloat162_rn(v0, v1);
            __nv_bfloat162 m = __floats2bfloat162_rn(v0 - __bfloat162float(h.x),
                                                     v1 - __bfloat162float(h.y));
            Ah[kt][reg] = bits2(h);
            Am[kt][reg] = bits2(m);
        }
    }
#pragma unroll
    for (int reg = 0; reg < 2; reg++) {
        const int row = reg ? r1 : r0;
        const int kk = 48 + 2 * i4;
        float v0 = 0.f, v1 = 0.f;
        if (row < HW) {
            int j0 = kk - row; if (j0 < 0) j0 += HW;
            int j1 = j0 + 1;   if (j1 == HW) j1 = 0;
            v0 = wtab[j0]; v1 = wtab[j1];
        }
        __nv_bfloat162 h = __floats2bfloat162_rn(v0, v1);
        __nv_bfloat162 m = __floats2bfloat162_rn(v0 - __bfloat162float(h.x),
                                                 v1 - __bfloat162float(h.y));
        Th[reg] = bits2(h);
        Tm[reg] = bits2(m);
    }

    // ---- convert pass: X -> natural [k][n] bf16 smem, hi & mid ----
    int kU[4], wqU[4];
#pragma unroll
    for (int i = 0; i < 4; i++) {
        const int u2 = tid + 256 * i;
        kU[i] = u2 / 14;
        wqU[i] = u2 - kU[i] * 14;
    }
    const float* xc = x + ((size_t)b0 * CCH + c) * PLANE;
#pragma unroll
    for (int b = 0; b < 4; b++) {
        const float* xb = xc + (size_t)b * CCH * PLANE;
        char* sb = smem + b * 112;
#pragma unroll
        for (int i = 0; i < 4; i++) {
            if (tid + 256 * i >= 784) break;
            const float4 v = *(const float4*)(xb + kU[i] * HW + wqU[i] * 4);
            __nv_bfloat162 h01 = __floats2bfloat162_rn(v.x, v.y);
            __nv_bfloat162 h23 = __floats2bfloat162_rn(v.z, v.w);
            __nv_bfloat162 m01 = __floats2bfloat162_rn(v.x - __bfloat162float(h01.x),
                                                       v.y - __bfloat162float(h01.y));
            __nv_bfloat162 m23 = __floats2bfloat162_rn(v.z - __bfloat162float(h23.x),
                                                       v.w - __bfloat162float(h23.y));
            char* p = sb + kU[i] * ROWB + wqU[i] * 8;
            *(uint2*)p = make_uint2(bits2(h01), bits2(h23));
            *(uint2*)(p + CH_STRIDE) = make_uint2(bits2(m01), bits2(m23));
        }
    }
    __syncthreads();

    // ---- MMA: warp = (m-quarter wm, n-half wn); kt-level register pipeline ----
    const float bv = bias[c];
    const uint32_t sbase = smem_u32(smem);
    const int krow = (lane & 7) + ((lane >> 3) & 1) * 8;
    const int nsel = lane >> 4;
    const int tnsel = (lane >> 3) & 1;
    const uint32_t lbase = sbase + krow * ROWB;
    const uint32_t tbase = sbase + (48 + (lane & 7)) * ROWB;

    uint32_t bh[2][4], bm[2][4];

#pragma unroll
    for (int np = 0; np < 7; np++) {
        const int nt0 = wn * 14 + np * 2;
        const uint32_t laddr = lbase + (uint32_t)(nt0 + nsel) * 16;
        const uint32_t taddr = tbase + (uint32_t)(nt0 + tnsel) * 16;
        if (np == 0) {                       // prime the pipeline
            ldmat4t(bh[0], laddr);
            ldmat4t(bm[0], laddr + CH_STRIDE);
        }
        float acc0[4] = {bv, bv, bv, bv};
        float acc1[4] = {bv, bv, bv, bv};
        uint32_t thr[2], tmr[2];
#pragma unroll
        for (int kt = 0; kt < 3; kt++) {
            const int cur = kt & 1, nxt = cur ^ 1;
            if (kt < 2) {                    // prefetch next k16 tile
                ldmat4t(bh[nxt], laddr + (kt + 1) * 16 * ROWB);
                ldmat4t(bm[nxt], laddr + (kt + 1) * 16 * ROWB + CH_STRIDE);
            } else {                         // prefetch k8 tail
                ldmat2t(thr, taddr);
                ldmat2t(tmr, taddr + CH_STRIDE);
            }
            mma16(acc0, Ah[kt], bh[cur][0], bh[cur][1]);
            mma16(acc1, Ah[kt], bh[cur][2], bh[cur][3]);
            mma16(acc0, Am[kt], bh[cur][0], bh[cur][1]);
            mma16(acc1, Am[kt], bh[cur][2], bh[cur][3]);
            mma16(acc0, Ah[kt], bm[cur][0], bm[cur][1]);
            mma16(acc1, Ah[kt], bm[cur][2], bm[cur][3]);
        }
        if (np < 6) {                        // prefetch next np's kt0
            const uint32_t laddr2 = lbase + (uint32_t)(nt0 + 2 + nsel) * 16;
            ldmat4t(bh[0], laddr2);
            ldmat4t(bm[0], laddr2 + CH_STRIDE);
        }
        mma8(acc0, Th, thr[0]);
        mma8(acc1, Th, thr[1]);
        mma8(acc0, Tm, thr[0]);
        mma8(acc1, Tm, thr[1]);
        mma8(acc0, Th, tmr[0]);
        mma8(acc1, Th, tmr[1]);
#pragma unroll
        for (int s = 0; s < 2; s++) {
            const float* acc = s ? acc1 : acc0;
            const int n = (nt0 + s) * 8 + 2 * i4;
            const int b = n / HW, wcol = n - b * HW;
            float* op = out + ((size_t)(b0 + b) * CCH + c) * PLANE + wcol;
            *(float2*)(op + r0 * HW) = make_float2(acc[0], acc[1]);
            if (wm != 3)
                *(float2*)(op + r1 * HW) = make_float2(acc[2], acc[3]);
        }
    }
}

extern "C" void kernel_launch(void* const* d_in, const int* in_sizes, int n_in,
                              void* d_out, int out_size) {
    const float* x      = (const float*)d_in[0];
    const float* weight = (const float*)d_in[1];
    const float* bias   = (const float*)d_in[2];
    cudaFuncSetAttribute(gcc_conv_hmma4,
                         cudaFuncAttributeMaxDynamicSharedMemorySize, SMEM_TOTAL);
    gcc_conv_hmma4<<<CCH * 8, NTHREADS, SMEM_TOTAL>>>(x, weight, bias, (float*)d_out);
}

// round 9
// speedup vs baseline: 1.2010x; 1.0612x over previous
#include <cuda_runtime.h>
#include <cuda_bf16.h>
#include <cstdint>

// Circulant GEMM on mma.sync bf16: D[56,112] = A_c[56,56] @ X[56,112]
// per (channel, 2 batches). 3-term split Ah*Bh + Am*Bh + Ah*Bm.
// K = 3 x k16 + k8 tail. B in natural [k][n] smem, ldmatrix.trans fetch,
// kt-level register double-buffer. 128-thread blocks -> 6 blocks/SM for
// cross-block phase overlap.

#define CCH 384
#define HW 56
#define PLANE 3136
#define NT 128
#define ROWB 240                      // 60 words/row, 60%32==28 -> conflict-free
#define CH_STRIDE (56 * ROWB)         // 13440 B per precision chunk
#define W_OFF (2 * CH_STRIDE)         // 26880
#define SMEM_TOTAL (W_OFF + 256)      // 27136 -> 6 blocks/SM

__device__ __forceinline__ uint32_t smem_u32(const void* p) {
    uint32_t a;
    asm("{ .reg .u64 t; cvta.to.shared.u64 t, %1; cvt.u32.u64 %0, t; }" : "=r"(a) : "l"(p));
    return a;
}
__device__ __forceinline__ void ldmat4t(uint32_t r[4], uint32_t addr) {
    asm volatile("ldmatrix.sync.aligned.m8n8.x4.trans.shared.b16 {%0,%1,%2,%3}, [%4];"
                 : "=r"(r[0]), "=r"(r[1]), "=r"(r[2]), "=r"(r[3]) : "r"(addr));
}
__device__ __forceinline__ void ldmat2t(uint32_t r[2], uint32_t addr) {
    asm volatile("ldmatrix.sync.aligned.m8n8.x2.trans.shared.b16 {%0,%1}, [%2];"
                 : "=r"(r[0]), "=r"(r[1]) : "r"(addr));
}
__device__ __forceinline__ void mma16(float c[4], const uint32_t a[4],
                                      uint32_t b0, uint32_t b1) {
    asm volatile(
        "mma.sync.aligned.m16n8k16.row.col.f32.bf16.bf16.f32 "
        "{%0,%1,%2,%3}, {%4,%5,%6,%7}, {%8,%9}, {%0,%1,%2,%3};"
        : "+f"(c[0]), "+f"(c[1]), "+f"(c[2]), "+f"(c[3])
        : "r"(a[0]), "r"(a[1]), "r"(a[2]), "r"(a[3]), "r"(b0), "r"(b1));
}
__device__ __forceinline__ void mma8(float c[4], const uint32_t a[2], uint32_t b0) {
    asm volatile(
        "mma.sync.aligned.m16n8k8.row.col.f32.bf16.bf16.f32 "
        "{%0,%1,%2,%3}, {%4,%5}, {%6}, {%0,%1,%2,%3};"
        : "+f"(c[0]), "+f"(c[1]), "+f"(c[2]), "+f"(c[3])
        : "r"(a[0]), "r"(a[1]), "r"(b0));
}
__device__ __forceinline__ uint32_t bits2(__nv_bfloat162 v) { return *(uint32_t*)&v; }

extern __shared__ char smem[];

__global__ __launch_bounds__(NT, 6)
void gcc_conv_hmma5(const float* __restrict__ x, const float* __restrict__ weight,
                    const float* __restrict__ bias, float* __restrict__ out) {
    const int tid = threadIdx.x;
    const int c  = blockIdx.x >> 4;
    const int b0 = (blockIdx.x & 15) * 2;

    float* wtab = (float*)(smem + W_OFF);
    if (tid < HW) wtab[tid] = weight[c * HW + tid];
    __syncthreads();

    const int wm = tid >> 5, lane = tid & 31;
    const int g = lane >> 2, i4 = lane & 3;
    const int r0 = wm * 16 + g;          // < 56
    const int r1 = r0 + 8;               // >= 56 only when wm==3

    // ---- A circulant fragments (hi/mid): 3 k16 tiles + k8 tail ----
    uint32_t Ah[3][4], Am[3][4], Th[2], Tm[2];
#pragma unroll
    for (int kt = 0; kt < 3; kt++) {
#pragma unroll
        for (int reg = 0; reg < 4; reg++) {
            const int row = (reg & 1) ? r1 : r0;
            const int kk = kt * 16 + 2 * i4 + ((reg & 2) ? 8 : 0);
            float v0 = 0.f, v1 = 0.f;
            if (row < HW) {
                int j0 = kk - row; if (j0 < 0) j0 += HW;
                int j1 = j0 + 1;   if (j1 == HW) j1 = 0;
                v0 = wtab[j0]; v1 = wtab[j1];
            }
            __nv_bfloat162 h = __floats2bfloat162_rn(v0, v1);
            __nv_bfloat162 m = __floats2bfloat162_rn(v0 - __bfloat162float(h.x),
                                                     v1 - __bfloat162float(h.y));
            Ah[kt][reg] = bits2(h);
            Am[kt][reg] = bits2(m);
        }
    }
#pragma unroll
    for (int reg = 0; reg < 2; reg++) {
        const int row = reg ? r1 : r0;
        const int kk = 48 + 2 * i4;
        float v0 = 0.f, v1 = 0.f;
        if (row < HW) {
            int j0 = kk - row; if (j0 < 0) j0 += HW;
            int j1 = j0 + 1;   if (j1 == HW) j1 = 0;
            v0 = wtab[j0]; v1 = wtab[j1];
        }
        __nv_bfloat162 h = __floats2bfloat162_rn(v0, v1);
        __nv_bfloat162 m = __floats2bfloat162_rn(v0 - __bfloat162float(h.x),
                                                 v1 - __bfloat162float(h.y));
        Th[reg] = bits2(h);
        Tm[reg] = bits2(m);
    }

    // ---- convert pass: X (2 batches) -> natural [k][n] bf16 smem, hi & mid ----
    const float* xc = x + ((size_t)b0 * CCH + c) * PLANE;
#pragma unroll
    for (int b = 0; b < 2; b++) {
        const float* xb = xc + (size_t)b * CCH * PLANE;
        char* sb = smem + b * 112;
#pragma unroll
        for (int i = 0; i < 7; i++) {
            const int u = tid + NT * i;
            if (u >= 784) break;
            const int k = u / 14, wq = u - k * 14;
            const float4 v = *(const float4*)(xb + k * HW + wq * 4);
            __nv_bfloat162 h01 = __floats2bfloat162_rn(v.x, v.y);
            __nv_bfloat162 h23 = __floats2bfloat162_rn(v.z, v.w);
            __nv_bfloat162 m01 = __floats2bfloat162_rn(v.x - __bfloat162float(h01.x),
                                                       v.y - __bfloat162float(h01.y));
            __nv_bfloat162 m23 = __floats2bfloat162_rn(v.z - __bfloat162float(h23.x),
                                                       v.w - __bfloat162float(h23.y));
            char* p = sb + k * ROWB + wq * 8;
            *(uint2*)p = make_uint2(bits2(h01), bits2(h23));
            *(uint2*)(p + CH_STRIDE) = make_uint2(bits2(m01), bits2(m23));
        }
    }
    __syncthreads();

    // ---- MMA: warp wm covers all 14 n-tiles (7 pairs); kt register pipeline ----
    const float bv = bias[c];
    const uint32_t sbase = smem_u32(smem);
    const int krow = (lane & 7) + ((lane >> 3) & 1) * 8;
    const int nsel = lane >> 4;
    const int tnsel = (lane >> 3) & 1;
    const uint32_t lbase = sbase + krow * ROWB;
    const uint32_t tbase = sbase + (48 + (lane & 7)) * ROWB;

    uint32_t bh[2][4], bm[2][4];

#pragma unroll
    for (int np = 0; np < 7; np++) {
        const int nt0 = np * 2;
        const uint32_t laddr = lbase + (uint32_t)(nt0 + nsel) * 16;
        const uint32_t taddr = tbase + (uint32_t)(nt0 + tnsel) * 16;
        if (np == 0) {                       // prime the pipeline
            ldmat4t(bh[0], laddr);
            ldmat4t(bm[0], laddr + CH_STRIDE);
        }
        float acc0[4] = {bv, bv, bv, bv};
        float acc1[4] = {bv, bv, bv, bv};
        uint32_t thr[2], tmr[2];
#pragma unroll
        for (int kt = 0; kt < 3; kt++) {
            const int cur = kt & 1, nxt = cur ^ 1;
            if (kt < 2) {                    // prefetch next k16 tile
                ldmat4t(bh[nxt], laddr + (kt + 1) * 16 * ROWB);
                ldmat4t(bm[nxt], laddr + (kt + 1) * 16 * ROWB + CH_STRIDE);
            } else {                         // prefetch k8 tail
                ldmat2t(thr, taddr);
                ldmat2t(tmr, taddr + CH_STRIDE);
            }
            mma16(acc0, Ah[kt], bh[cur][0], bh[cur][1]);
            mma16(acc1, Ah[kt], bh[cur][2], bh[cur][3]);
            mma16(acc0, Am[kt], bh[cur][0], bh[cur][1]);
            mma16(acc1, Am[kt], bh[cur][2], bh[cur][3]);
            mma16(acc0, Ah[kt], bm[cur][0], bm[cur][1]);
            mma16(acc1, Ah[kt], bm[cur][2], bm[cur][3]);
        }
        if (np < 6) {                        // prefetch next pair's kt0
            const uint32_t laddr2 = lbase + (uint32_t)(nt0 + 2 + nsel) * 16;
            ldmat4t(bh[0], laddr2);
            ldmat4t(bm[0], laddr2 + CH_STRIDE);
        }
        mma8(acc0, Th, thr[0]);
        mma8(acc1, Th, thr[1]);
        mma8(acc0, Tm, thr[0]);
        mma8(acc1, Tm, thr[1]);
        mma8(acc0, Th, tmr[0]);
        mma8(acc1, Th, tmr[1]);
#pragma unroll
        for (int s = 0; s < 2; s++) {
            const float* acc = s ? acc1 : acc0;
            const int n = (nt0 + s) * 8 + 2 * i4;
            const int b = (n >= HW);
            const int wcol = n - b * HW;
            float* op = out + ((size_t)(b0 + b) * CCH + c) * PLANE + wcol;
            *(float2*)(op + r0 * HW) = make_float2(acc[0], acc[1]);
            if (wm != 3)
                *(float2*)(op + r1 * HW) = make_float2(acc[2], acc[3]);
        }
    }
}

extern "C" void kernel_launch(void* const* d_in, const int* in_sizes, int n_in,
                              void* d_out, int out_size) {
    const float* x      = (const float*)d_in[0];
    const float* weight = (const float*)d_in[1];
    const float* bias   = (const float*)d_in[2];
    cudaFuncSetAttribute(gcc_conv_hmma5,
                         cudaFuncAttributeMaxDynamicSharedMemorySize, SMEM_TOTAL);
    gcc_conv_hmma5<<<CCH * 16, NT, SMEM_TOTAL>>>(x, weight, bias, (float*)d_out);
}

// round 10
// speedup vs baseline: 1.4517x; 1.2088x over previous
#include <cuda_runtime.h>
#include <cuda_fp16.h>
#include <cstdint>

// Circulant GEMM on mma.sync fp16: D[56,112] = A_c[56,56] @ X[56,112]
// per (channel, 2 batches). fp16 2-term split: (Ah + Am) @ Bh where
// Ah = fp16(w), Am = fp16(w - Ah), Bh = fp16(x). Dropped error w*(x-xh)
// ~2^-12/product -> norm rel_err ~1e-4 << 1e-3.
// K = 3 x k16 + k8 tail. B in natural [k][n] smem, ldmatrix.trans fetch,
// kt-level register double-buffer. 128-thread blocks.

#define CCH 384
#define HW 56
#define PLANE 3136
#define NT 128
#define ROWB 240                      // 60 words/row, 60%32==28 -> conflict-free
#define W_OFF (56 * ROWB)             // 13440
#define SMEM_TOTAL (W_OFF + 256)      // 13696

__device__ __forceinline__ uint32_t smem_u32(const void* p) {
    uint32_t a;
    asm("{ .reg .u64 t; cvta.to.shared.u64 t, %1; cvt.u32.u64 %0, t; }" : "=r"(a) : "l"(p));
    return a;
}
__device__ __forceinline__ void ldmat4t(uint32_t r[4], uint32_t addr) {
    asm volatile("ldmatrix.sync.aligned.m8n8.x4.trans.shared.b16 {%0,%1,%2,%3}, [%4];"
                 : "=r"(r[0]), "=r"(r[1]), "=r"(r[2]), "=r"(r[3]) : "r"(addr));
}
__device__ __forceinline__ void ldmat2t(uint32_t r[2], uint32_t addr) {
    asm volatile("ldmatrix.sync.aligned.m8n8.x2.trans.shared.b16 {%0,%1}, [%2];"
                 : "=r"(r[0]), "=r"(r[1]) : "r"(addr));
}
__device__ __forceinline__ void mma16(float c[4], const uint32_t a[4],
                                      uint32_t b0, uint32_t b1) {
    asm volatile(
        "mma.sync.aligned.m16n8k16.row.col.f32.f16.f16.f32 "
        "{%0,%1,%2,%3}, {%4,%5,%6,%7}, {%8,%9}, {%0,%1,%2,%3};"
        : "+f"(c[0]), "+f"(c[1]), "+f"(c[2]), "+f"(c[3])
        : "r"(a[0]), "r"(a[1]), "r"(a[2]), "r"(a[3]), "r"(b0), "r"(b1));
}
__device__ __forceinline__ void mma8(float c[4], const uint32_t a[2], uint32_t b0) {
    asm volatile(
        "mma.sync.aligned.m16n8k8.row.col.f32.f16.f16.f32 "
        "{%0,%1,%2,%3}, {%4,%5}, {%6}, {%0,%1,%2,%3};"
        : "+f"(c[0]), "+f"(c[1]), "+f"(c[2]), "+f"(c[3])
        : "r"(a[0]), "r"(a[1]), "r"(b0));
}
__device__ __forceinline__ uint32_t bits2h(__half2 v) { return *(uint32_t*)&v; }

extern __shared__ char smem[];

__global__ __launch_bounds__(NT, 6)
void gcc_conv_hmma6(const float* __restrict__ x, const float* __restrict__ weight,
                    const float* __restrict__ bias, float* __restrict__ out) {
    const int tid = threadIdx.x;
    const int c  = blockIdx.x >> 4;
    const int b0 = (blockIdx.x & 15) * 2;

    float* wtab = (float*)(smem + W_OFF);
    if (tid < HW) wtab[tid] = weight[c * HW + tid];
    __syncthreads();

    const int wm = tid >> 5, lane = tid & 31;
    const int g = lane >> 2, i4 = lane & 3;
    const int r0 = wm * 16 + g;          // < 56
    const int r1 = r0 + 8;               // >= 56 only when wm==3

    // ---- A circulant fragments (hi/mid fp16): 3 k16 tiles + k8 tail ----
    uint32_t Ah[3][4], Am[3][4], Th[2], Tm[2];
#pragma unroll
    for (int kt = 0; kt < 3; kt++) {
#pragma unroll
        for (int reg = 0; reg < 4; reg++) {
            const int row = (reg & 1) ? r1 : r0;
            const int kk = kt * 16 + 2 * i4 + ((reg & 2) ? 8 : 0);
            float v0 = 0.f, v1 = 0.f;
            if (row < HW) {
                int j0 = kk - row; if (j0 < 0) j0 += HW;
                int j1 = j0 + 1;   if (j1 == HW) j1 = 0;
                v0 = wtab[j0]; v1 = wtab[j1];
            }
            __half h0 = __float2half_rn(v0), h1 = __float2half_rn(v1);
            __half m0 = __float2half_rn(v0 - __half2float(h0));
            __half m1 = __float2half_rn(v1 - __half2float(h1));
            Ah[kt][reg] = bits2h(__halves2half2(h0, h1));
            Am[kt][reg] = bits2h(__halves2half2(m0, m1));
        }
    }
#pragma unroll
    for (int reg = 0; reg < 2; reg++) {
        const int row = reg ? r1 : r0;
        const int kk = 48 + 2 * i4;
        float v0 = 0.f, v1 = 0.f;
        if (row < HW) {
            int j0 = kk - row; if (j0 < 0) j0 += HW;
            int j1 = j0 + 1;   if (j1 == HW) j1 = 0;
            v0 = wtab[j0]; v1 = wtab[j1];
        }
        __half h0 = __float2half_rn(v0), h1 = __float2half_rn(v1);
        __half m0 = __float2half_rn(v0 - __half2float(h0));
        __half m1 = __float2half_rn(v1 - __half2float(h1));
        Th[reg] = bits2h(__halves2half2(h0, h1));
        Tm[reg] = bits2h(__halves2half2(m0, m1));
    }

    // ---- convert pass: X (2 batches) -> natural [k][n] fp16 smem ----
    const float* xc = x + ((size_t)b0 * CCH + c) * PLANE;
#pragma unroll
    for (int b = 0; b < 2; b++) {
        const float* xb = xc + (size_t)b * CCH * PLANE;
        char* sb = smem + b * 112;
#pragma unroll
        for (int i = 0; i < 7; i++) {
            const int u = tid + NT * i;
            if (u >= 784) break;
            const int k = u / 14, wq = u - k * 14;
            const float4 v = *(const float4*)(xb + k * HW + wq * 4);
            uint2 pk;
            pk.x = bits2h(__floats2half2_rn(v.x, v.y));
            pk.y = bits2h(__floats2half2_rn(v.z, v.w));
            *(uint2*)(sb + k * ROWB + wq * 8) = pk;
        }
    }
    __syncthreads();

    // ---- MMA: warp wm covers all 14 n-tiles (7 pairs); kt register pipeline ----
    const float bv = bias[c];
    const uint32_t sbase = smem_u32(smem);
    const int krow = (lane & 7) + ((lane >> 3) & 1) * 8;
    const int nsel = lane >> 4;
    const int tnsel = (lane >> 3) & 1;
    const uint32_t lbase = sbase + krow * ROWB;
    const uint32_t tbase = sbase + (48 + (lane & 7)) * ROWB;

    uint32_t bh[2][4];

#pragma unroll
    for (int np = 0; np < 7; np++) {
        const int nt0 = np * 2;
        const uint32_t laddr = lbase + (uint32_t)(nt0 + nsel) * 16;
        const uint32_t taddr = tbase + (uint32_t)(nt0 + tnsel) * 16;
        if (np == 0)                          // prime the pipeline
            ldmat4t(bh[0], laddr);
        float acc0[4] = {bv, bv, bv, bv};
        float acc1[4] = {bv, bv, bv, bv};
        uint32_t thr[2];
#pragma unroll
        for (int kt = 0; kt < 3; kt++) {
            const int cur = kt & 1, nxt = cur ^ 1;
            if (kt < 2)                       // prefetch next k16 tile
                ldmat4t(bh[nxt], laddr + (kt + 1) * 16 * ROWB);
            else                              // prefetch k8 tail
                ldmat2t(thr, taddr);
            mma16(acc0, Ah[kt], bh[cur][0], bh[cur][1]);
            mma16(acc1, Ah[kt], bh[cur][2], bh[cur][3]);
            mma16(acc0, Am[kt], bh[cur][0], bh[cur][1]);
            mma16(acc1, Am[kt], bh[cur][2], bh[cur][3]);
        }
        if (np < 6) {                         // prefetch next pair's kt0
            const uint32_t laddr2 = lbase + (uint32_t)(nt0 + 2 + nsel) * 16;
            ldmat4t(bh[0], laddr2);
        }
        mma8(acc0, Th, thr[0]);
        mma8(acc1, Th, thr[1]);
        mma8(acc0, Tm, thr[0]);
        mma8(acc1, Tm, thr[1]);
#pragma unroll
        for (int s = 0; s < 2; s++) {
            const float* acc = s ? acc1 : acc0;
            const int n = (nt0 + s) * 8 + 2 * i4;
            const int b = (n >= HW);
            const int wcol = n - b * HW;
            float* op = out + ((size_t)(b0 + b) * CCH + c) * PLANE + wcol;
            *(float2*)(op + r0 * HW) = make_float2(acc[0], acc[1]);
            if (wm != 3)
                *(float2*)(op + r1 * HW) = make_float2(acc[2], acc[3]);
        }
    }
}

extern "C" void kernel_launch(void* const* d_in, const int* in_sizes, int n_in,
                              void* d_out, int out_size) {
    const float* x      = (const float*)d_in[0];
    const float* weight = (const float*)d_in[1];
    const float* bias   = (const float*)d_in[2];
    cudaFuncSetAttribute(gcc_conv_hmma6,
                         cudaFuncAttributeMaxDynamicSharedMemorySize, SMEM_TOTAL);
    gcc_conv_hmma6<<<CCH * 16, NT, SMEM_TOTAL>>>(x, weight, bias, (float*)d_out);
}